// round 2
// baseline (speedup 1.0000x reference)
#include <cuda_runtime.h>

#define RR 256
#define CC 32
#define SS 8
#define HH 32
#define WARPS 4
#define FPAD 36          // padded feat row stride (words): conflict-free for .32 and .128
#define PTS_PER_WARP 64

// shared-memory float offsets
#define SM_W0    0
#define SM_W1    1024
#define SM_CW0   2048
#define SM_CW1   3072
#define SM_B0    4096
#define SM_B1    4128
#define SM_CB0   4160
#define SM_CB1   4192
#define SM_WOUT  4224
#define SM_CWOUT 4256
#define SM_BND   4352
#define SM_BO    4400
#define SM_CBO   4404
#define SM_FEAT  4416
#define SMEM_FLOATS (SM_FEAT + WARPS * PTS_PER_WARP * FPAD)   // 13632 -> 54528 B

__device__ __forceinline__ float bil(const float* __restrict__ pl, int o, int lane,
                                     float wx, float wy) {
    const float a = 1.0f - wx, b = 1.0f - wy;
    const float* q = pl + o * CC + lane;
    return (a * b) * q[0] + (wx * b) * q[CC] + (a * wy) * q[RR * CC] + (wx * wy) * q[RR * CC + CC];
}

__device__ __forceinline__ void gather_branch(
    const float* __restrict__ P0, const float* __restrict__ P1, const float* __restrict__ P2,
    float* __restrict__ sfeat, int lane,
    const int (&o0)[2], const int (&o1)[2], const int (&o2)[2],
    const float (&wx0)[2], const float (&wy0)[2],
    const float (&wx1)[2], const float (&wy1)[2],
    const float (&wx2)[2], const float (&wy2)[2],
    const unsigned (&vm)[2])
{
    #pragma unroll
    for (int half = 0; half < 2; half++) {
        const unsigned v = vm[half];
        #pragma unroll 1
        for (int pt = 0; pt < 32; pt++) {
            const int   c0 = __shfl_sync(0xffffffffu, o0[half], pt);
            const int   c1 = __shfl_sync(0xffffffffu, o1[half], pt);
            const int   c2 = __shfl_sync(0xffffffffu, o2[half], pt);
            const float a0 = __shfl_sync(0xffffffffu, wx0[half], pt);
            const float b0 = __shfl_sync(0xffffffffu, wy0[half], pt);
            const float a1 = __shfl_sync(0xffffffffu, wx1[half], pt);
            const float b1 = __shfl_sync(0xffffffffu, wy1[half], pt);
            const float a2 = __shfl_sync(0xffffffffu, wx2[half], pt);
            const float b2 = __shfl_sync(0xffffffffu, wy2[half], pt);
            float f = bil(P0, c0, lane, a0, b0)
                    + bil(P1, c1, lane, a1, b1)
                    + bil(P2, c2, lane, a2, b2);
            const float m = ((v >> pt) & 1u) ? 1.0f : 0.0f;
            sfeat[(half * 32 + pt) * FPAD + lane] = f * m;
        }
    }
}

// two-layer MLP for 2 points (rows lane and lane+32 of sfeat); leaves pre-relu
// layer-2 activations in hA/hB. Stages relu(layer1) through sfeat (own rows only).
__device__ __forceinline__ void mlp2(
    float* __restrict__ sfeat, int lane,
    const float* __restrict__ W0, const float* __restrict__ B0,
    const float* __restrict__ W1, const float* __restrict__ B1,
    float (&hA)[HH], float (&hB)[HH])
{
    #pragma unroll
    for (int j4 = 0; j4 < 8; j4++) {
        const float4 b = *(const float4*)&B0[j4 * 4];
        hA[j4*4+0] = b.x; hA[j4*4+1] = b.y; hA[j4*4+2] = b.z; hA[j4*4+3] = b.w;
        hB[j4*4+0] = b.x; hB[j4*4+1] = b.y; hB[j4*4+2] = b.z; hB[j4*4+3] = b.w;
    }
    #pragma unroll 1
    for (int i4 = 0; i4 < 8; i4++) {
        const float4 fav = *(const float4*)&sfeat[lane * FPAD + i4 * 4];
        const float4 fbv = *(const float4*)&sfeat[(lane + 32) * FPAD + i4 * 4];
        const float fa[4] = {fav.x, fav.y, fav.z, fav.w};
        const float fb[4] = {fbv.x, fbv.y, fbv.z, fbv.w};
        #pragma unroll
        for (int k = 0; k < 4; k++) {
            const float4* wr = (const float4*)&W0[(i4 * 4 + k) * HH];
            const float f1 = fa[k], f2 = fb[k];
            #pragma unroll
            for (int j4 = 0; j4 < 8; j4++) {
                const float4 w = wr[j4];
                hA[j4*4+0] += f1 * w.x; hB[j4*4+0] += f2 * w.x;
                hA[j4*4+1] += f1 * w.y; hB[j4*4+1] += f2 * w.y;
                hA[j4*4+2] += f1 * w.z; hB[j4*4+2] += f2 * w.z;
                hA[j4*4+3] += f1 * w.w; hB[j4*4+3] += f2 * w.w;
            }
        }
    }
    // stage relu(layer1) back through own sfeat rows
    #pragma unroll
    for (int i4 = 0; i4 < 8; i4++) {
        float4 ra, rb;
        ra.x = fmaxf(hA[i4*4+0], 0.0f); ra.y = fmaxf(hA[i4*4+1], 0.0f);
        ra.z = fmaxf(hA[i4*4+2], 0.0f); ra.w = fmaxf(hA[i4*4+3], 0.0f);
        rb.x = fmaxf(hB[i4*4+0], 0.0f); rb.y = fmaxf(hB[i4*4+1], 0.0f);
        rb.z = fmaxf(hB[i4*4+2], 0.0f); rb.w = fmaxf(hB[i4*4+3], 0.0f);
        *(float4*)&sfeat[lane * FPAD + i4 * 4] = ra;
        *(float4*)&sfeat[(lane + 32) * FPAD + i4 * 4] = rb;
    }
    // layer 2
    #pragma unroll
    for (int j4 = 0; j4 < 8; j4++) {
        const float4 b = *(const float4*)&B1[j4 * 4];
        hA[j4*4+0] = b.x; hA[j4*4+1] = b.y; hA[j4*4+2] = b.z; hA[j4*4+3] = b.w;
        hB[j4*4+0] = b.x; hB[j4*4+1] = b.y; hB[j4*4+2] = b.z; hB[j4*4+3] = b.w;
    }
    #pragma unroll 1
    for (int i4 = 0; i4 < 8; i4++) {
        const float4 fav = *(const float4*)&sfeat[lane * FPAD + i4 * 4];
        const float4 fbv = *(const float4*)&sfeat[(lane + 32) * FPAD + i4 * 4];
        const float fa[4] = {fav.x, fav.y, fav.z, fav.w};
        const float fb[4] = {fbv.x, fbv.y, fbv.z, fbv.w};
        #pragma unroll
        for (int k = 0; k < 4; k++) {
            const float4* wr = (const float4*)&W1[(i4 * 4 + k) * HH];
            const float f1 = fa[k], f2 = fb[k];
            #pragma unroll
            for (int j4 = 0; j4 < 8; j4++) {
                const float4 w = wr[j4];
                hA[j4*4+0] += f1 * w.x; hB[j4*4+0] += f2 * w.x;
                hA[j4*4+1] += f1 * w.y; hB[j4*4+1] += f2 * w.y;
                hA[j4*4+2] += f1 * w.z; hB[j4*4+2] += f2 * w.z;
                hA[j4*4+3] += f1 * w.w; hB[j4*4+3] += f2 * w.w;
            }
        }
    }
}

__global__ __launch_bounds__(128) void decoders_kernel(
    const float* __restrict__ p,
    const float* __restrict__ boundaries,
    const float* __restrict__ pxy, const float* __restrict__ pxz, const float* __restrict__ pyz,
    const float* __restrict__ cxy, const float* __restrict__ cxz, const float* __restrict__ cyz,
    const float* __restrict__ w0, const float* __restrict__ b0,
    const float* __restrict__ w1, const float* __restrict__ b1,
    const float* __restrict__ w_out, const float* __restrict__ b_out,
    const float* __restrict__ cw0, const float* __restrict__ cb0,
    const float* __restrict__ cw1, const float* __restrict__ cb1,
    const float* __restrict__ cw_out, const float* __restrict__ cb_out,
    float* __restrict__ out, int n)
{
    extern __shared__ float smem[];
    const int tid = threadIdx.x;

    for (int i = tid; i < CC * HH; i += 128) {
        smem[SM_W0 + i]  = w0[i];   smem[SM_W1 + i]  = w1[i];
        smem[SM_CW0 + i] = cw0[i];  smem[SM_CW1 + i] = cw1[i];
    }
    if (tid < HH) {
        smem[SM_B0 + tid]   = b0[tid];  smem[SM_B1 + tid]  = b1[tid];
        smem[SM_CB0 + tid]  = cb0[tid]; smem[SM_CB1 + tid] = cb1[tid];
        smem[SM_WOUT + tid] = w_out[tid];
    }
    if (tid < HH * 3) smem[SM_CWOUT + tid] = cw_out[tid];
    if (tid < SS * 6) smem[SM_BND + tid] = boundaries[tid];
    if (tid == 0) smem[SM_BO] = b_out[0];
    if (tid < 3) smem[SM_CBO + tid] = cb_out[tid];
    __syncthreads();

    const int warp = tid >> 5, lane = tid & 31;
    const int base = (blockIdx.x * WARPS + warp) * PTS_PER_WARP;
    float* __restrict__ sfeat = smem + SM_FEAT + warp * (PTS_PER_WARP * FPAD);
    const float* sbnd = smem + SM_BND;

    // ---- per-thread params for 2 points ----
    int   o0[2], o1[2], o2[2];
    float wx0[2], wy0[2], wx1[2], wy1[2], wx2[2], wy2[2];
    unsigned vm[2];

    #pragma unroll
    for (int half = 0; half < 2; half++) {
        const int idx = base + half * 32 + lane;
        float px = 2.0f, py = 2.0f, pz = 2.0f;
        if (idx < n) { px = p[idx*3]; py = p[idx*3+1]; pz = p[idx*3+2]; }

        int s = 0; bool valid = false;
        #pragma unroll
        for (int k = SS - 1; k >= 0; k--) {
            const float lx = sbnd[k*6+0], ly = sbnd[k*6+1], lz = sbnd[k*6+2];
            const float hx = sbnd[k*6+3], hy = sbnd[k*6+4], hz = sbnd[k*6+5];
            const bool in = (px > lx) & (px < hx) & (py > ly) & (py < hy) & (pz > lz) & (pz < hz);
            if (in) { s = k; valid = true; }
        }
        vm[half] = __ballot_sync(0xffffffffu, valid);

        const float bx0 = sbnd[s*6+0], by0 = sbnd[s*6+1], bz0 = sbnd[s*6+2];
        const float bx1 = sbnd[s*6+3], by1 = sbnd[s*6+4], bz1 = sbnd[s*6+5];
        const float pnx = (px - bx0) / (bx1 - bx0) * 2.0f - 1.0f;
        const float pny = (py - by0) / (by1 - by0) * 2.0f - 1.0f;
        const float pnz = (pz - bz0) / (bz1 - bz0) * 2.0f - 1.0f;

        const float us[3] = { pnx, pnx, pny };
        const float vs[3] = { pny, pnz, pnz };
        int xs[3], ys[3]; float wxs[3], wys[3];
        #pragma unroll
        for (int t = 0; t < 3; t++) {
            const float x = (us[t] + 1.0f) * 0.5f * (float)(RR - 1);
            const float y = (vs[t] + 1.0f) * 0.5f * (float)(RR - 1);
            const float xf = fminf(fmaxf(floorf(x), 0.0f), (float)(RR - 2));
            const float yf = fminf(fmaxf(floorf(y), 0.0f), (float)(RR - 2));
            xs[t] = (int)xf; ys[t] = (int)yf;
            wxs[t] = x - xf; wys[t] = y - yf;
        }
        o0[half] = (s * RR + ys[0]) * RR + xs[0];
        o1[half] = (s * RR + ys[1]) * RR + xs[1];
        o2[half] = (s * RR + ys[2]) * RR + xs[2];
        wx0[half] = wxs[0]; wy0[half] = wys[0];
        wx1[half] = wxs[1]; wy1[half] = wys[1];
        wx2[half] = wxs[2]; wy2[half] = wys[2];
    }

    float hA[HH], hB[HH];

    // ================= SDF branch =================
    gather_branch(pxy, pxz, pyz, sfeat, lane, o0, o1, o2,
                  wx0, wy0, wx1, wy1, wx2, wy2, vm);
    __syncwarp();
    mlp2(sfeat, lane, smem + SM_W0, smem + SM_B0, smem + SM_W1, smem + SM_B1, hA, hB);

    float sdfA, sdfB;
    {
        const float bo = smem[SM_BO];
        float accA = bo, accB = bo;
        #pragma unroll
        for (int j4 = 0; j4 < 8; j4++) {
            const float4 w = *(const float4*)&smem[SM_WOUT + j4 * 4];
            accA += fmaxf(hA[j4*4+0], 0.0f) * w.x; accB += fmaxf(hB[j4*4+0], 0.0f) * w.x;
            accA += fmaxf(hA[j4*4+1], 0.0f) * w.y; accB += fmaxf(hB[j4*4+1], 0.0f) * w.y;
            accA += fmaxf(hA[j4*4+2], 0.0f) * w.z; accB += fmaxf(hB[j4*4+2], 0.0f) * w.z;
            accA += fmaxf(hA[j4*4+3], 0.0f) * w.w; accB += fmaxf(hB[j4*4+3], 0.0f) * w.w;
        }
        sdfA = tanhf(accA); sdfB = tanhf(accB);
    }
    __syncwarp();

    // ================= Color branch =================
    gather_branch(cxy, cxz, cyz, sfeat, lane, o0, o1, o2,
                  wx0, wy0, wx1, wy1, wx2, wy2, vm);
    __syncwarp();
    mlp2(sfeat, lane, smem + SM_CW0, smem + SM_CB0, smem + SM_CW1, smem + SM_CB1, hA, hB);

    float rA = smem[SM_CBO+0], gA = smem[SM_CBO+1], bA = smem[SM_CBO+2];
    float rB = rA, gB = gA, bB = bA;
    #pragma unroll
    for (int j = 0; j < HH; j++) {
        const float hvA = fmaxf(hA[j], 0.0f);
        const float hvB = fmaxf(hB[j], 0.0f);
        const float c0 = smem[SM_CWOUT + j*3 + 0];
        const float c1 = smem[SM_CWOUT + j*3 + 1];
        const float c2 = smem[SM_CWOUT + j*3 + 2];
        rA += hvA * c0; rB += hvB * c0;
        gA += hvA * c1; gB += hvB * c1;
        bA += hvA * c2; bB += hvB * c2;
    }

    const int idxA = base + lane;
    const int idxB = base + 32 + lane;
    if (idxA < n) {
        float4 o;
        o.x = 1.0f / (1.0f + expf(-rA));
        o.y = 1.0f / (1.0f + expf(-gA));
        o.z = 1.0f / (1.0f + expf(-bA));
        o.w = sdfA;
        ((float4*)out)[idxA] = o;
    }
    if (idxB < n) {
        float4 o;
        o.x = 1.0f / (1.0f + expf(-rB));
        o.y = 1.0f / (1.0f + expf(-gB));
        o.z = 1.0f / (1.0f + expf(-bB));
        o.w = sdfB;
        ((float4*)out)[idxB] = o;
    }
}

extern "C" void kernel_launch(void* const* d_in, const int* in_sizes, int n_in,
                              void* d_out, int out_size) {
    const float* p          = (const float*)d_in[0];
    const float* boundaries = (const float*)d_in[1];
    const float* pxy        = (const float*)d_in[2];
    const float* pxz        = (const float*)d_in[3];
    const float* pyz        = (const float*)d_in[4];
    const float* cxy        = (const float*)d_in[5];
    const float* cxz        = (const float*)d_in[6];
    const float* cyz        = (const float*)d_in[7];
    const float* w0         = (const float*)d_in[8];
    const float* b0         = (const float*)d_in[9];
    const float* w1         = (const float*)d_in[10];
    const float* b1         = (const float*)d_in[11];
    const float* w_out      = (const float*)d_in[12];
    const float* b_out      = (const float*)d_in[13];
    const float* cw0        = (const float*)d_in[14];
    const float* cb0        = (const float*)d_in[15];
    const float* cw1        = (const float*)d_in[16];
    const float* cb1        = (const float*)d_in[17];
    const float* cw_out     = (const float*)d_in[18];
    const float* cb_out     = (const float*)d_in[19];

    const int n = in_sizes[0] / 3;
    float* out = (float*)d_out;

    const int smem_bytes = SMEM_FLOATS * (int)sizeof(float);
    cudaFuncSetAttribute(decoders_kernel,
                         cudaFuncAttributeMaxDynamicSharedMemorySize, smem_bytes);

    const int pts_per_block = WARPS * PTS_PER_WARP;   // 256
    const int blocks = (n + pts_per_block - 1) / pts_per_block;
    decoders_kernel<<<blocks, 128, smem_bytes>>>(
        p, boundaries, pxy, pxz, pyz, cxy, cxz, cyz,
        w0, b0, w1, b1, w_out, b_out,
        cw0, cb0, cw1, cb1, cw_out, cb_out,
        out, n);
}

// round 3
// speedup vs baseline: 1.3818x; 1.3818x over previous
#include <cuda_runtime.h>

typedef unsigned long long ull;

#define RR 256
#define CC 32
#define SS 8
#define HH 32
#define WARPS 4
#define FPAD 36

// shared-memory float offsets
#define SM_W0    0
#define SM_W1    1024
#define SM_CW0   2048
#define SM_CW1   3072
#define SM_B0    4096
#define SM_B1    4128
#define SM_CB0   4160
#define SM_CB1   4192
#define SM_WOUT  4224
#define SM_CWOUT 4256
#define SM_BND   4352
#define SM_BO    4400
#define SM_CBO   4404
#define SM_PAR   4416                       // WARPS*32*16 = 2048 words
#define SM_FEAT  (SM_PAR + WARPS*32*16)     // 6464; WARPS*32*FPAD = 4608 words
#define SMEM_FLOATS (SM_FEAT + WARPS*32*FPAD)   // 11072 words = 44288 B

__device__ __forceinline__ ull pack2(float lo, float hi) {
    ull d; asm("mov.b64 %0, {%1, %2};" : "=l"(d) : "f"(lo), "f"(hi)); return d;
}
__device__ __forceinline__ void unpack2(ull v, float& lo, float& hi) {
    asm("mov.b64 {%0, %1}, %2;" : "=f"(lo), "=f"(hi) : "l"(v));
}
__device__ __forceinline__ void fma2(ull& d, ull a, ull b) {
    asm("fma.rn.f32x2 %0, %1, %2, %0;" : "+l"(d) : "l"(a), "l"(b));
}

// one 32x32 layer, packed f32x2 accumulators; src = this lane's smem row
__device__ __forceinline__ void layer32(const float* __restrict__ row,
                                        const float* __restrict__ W,
                                        const float* __restrict__ B,
                                        ull (&h)[16])
{
    const ulonglong2* Bv = (const ulonglong2*)B;
    #pragma unroll
    for (int j = 0; j < 8; j++) { ulonglong2 b = Bv[j]; h[2*j] = b.x; h[2*j+1] = b.y; }
    #pragma unroll
    for (int i4 = 0; i4 < 8; i4++) {
        const float4 f4 = *(const float4*)&row[i4 * 4];
        const float fk[4] = { f4.x, f4.y, f4.z, f4.w };
        #pragma unroll
        for (int k = 0; k < 4; k++) {
            const ull a = pack2(fk[k], fk[k]);
            const ulonglong2* wr = (const ulonglong2*)&W[(i4 * 4 + k) * HH];
            #pragma unroll
            for (int j = 0; j < 8; j++) {
                const ulonglong2 w = wr[j];
                fma2(h[2*j],   a, w.x);
                fma2(h[2*j+1], a, w.y);
            }
        }
    }
}

__device__ __forceinline__ void relu_store(float* __restrict__ row, const ull (&h)[16])
{
    #pragma unroll
    for (int j = 0; j < 8; j++) {
        float a, b, c, d;
        unpack2(h[2*j], a, b); unpack2(h[2*j+1], c, d);
        float4 v;
        v.x = fmaxf(a, 0.0f); v.y = fmaxf(b, 0.0f);
        v.z = fmaxf(c, 0.0f); v.w = fmaxf(d, 0.0f);
        *(float4*)&row[j * 4] = v;
    }
}

// warp-cooperative gather: lane = channel, one point per iteration
__device__ __forceinline__ void gather32(
    const float* __restrict__ P0, const float* __restrict__ P1, const float* __restrict__ P2,
    const float* __restrict__ par, float* __restrict__ sfeat, int lane)
{
    #pragma unroll 4
    for (int pt = 0; pt < 32; pt++) {
        const float4 q0 = *(const float4*)&par[pt * 16 + 0];
        const float4 q1 = *(const float4*)&par[pt * 16 + 4];
        const float4 q2 = *(const float4*)&par[pt * 16 + 8];
        const int4  qo = *(const int4*) &par[pt * 16 + 12];
        const float* a = P0 + qo.x + lane;
        const float* b = P1 + qo.y + lane;
        const float* c = P2 + qo.z + lane;
        float f;
        f  = q0.x * a[0] + q0.y * a[CC] + q0.z * a[RR*CC] + q0.w * a[RR*CC + CC];
        f += q1.x * b[0] + q1.y * b[CC] + q1.z * b[RR*CC] + q1.w * b[RR*CC + CC];
        f += q2.x * c[0] + q2.y * c[CC] + q2.z * c[RR*CC] + q2.w * c[RR*CC + CC];
        sfeat[pt * FPAD + lane] = f;
    }
}

__global__ __launch_bounds__(128, 5) void decoders_kernel(
    const float* __restrict__ p,
    const float* __restrict__ boundaries,
    const float* __restrict__ pxy, const float* __restrict__ pxz, const float* __restrict__ pyz,
    const float* __restrict__ cxy, const float* __restrict__ cxz, const float* __restrict__ cyz,
    const float* __restrict__ w0, const float* __restrict__ b0,
    const float* __restrict__ w1, const float* __restrict__ b1,
    const float* __restrict__ w_out, const float* __restrict__ b_out,
    const float* __restrict__ cw0, const float* __restrict__ cb0,
    const float* __restrict__ cw1, const float* __restrict__ cb1,
    const float* __restrict__ cw_out, const float* __restrict__ cb_out,
    float* __restrict__ out, int n)
{
    extern __shared__ float smem[];
    const int tid = threadIdx.x;

    for (int i = tid; i < CC * HH; i += 128) {
        smem[SM_W0 + i]  = w0[i];   smem[SM_W1 + i]  = w1[i];
        smem[SM_CW0 + i] = cw0[i];  smem[SM_CW1 + i] = cw1[i];
    }
    if (tid < HH) {
        smem[SM_B0 + tid]   = b0[tid];  smem[SM_B1 + tid]  = b1[tid];
        smem[SM_CB0 + tid]  = cb0[tid]; smem[SM_CB1 + tid] = cb1[tid];
        smem[SM_WOUT + tid] = w_out[tid];
    }
    if (tid < HH * 3) smem[SM_CWOUT + tid] = cw_out[tid];
    if (tid < SS * 6) smem[SM_BND + tid] = boundaries[tid];
    if (tid == 0) smem[SM_BO] = b_out[0];
    if (tid < 3) smem[SM_CBO + tid] = cb_out[tid];
    __syncthreads();

    const int warp = tid >> 5, lane = tid & 31;
    const int base = (blockIdx.x * WARPS + warp) * 32;
    float* __restrict__ par   = smem + SM_PAR  + warp * (32 * 16);
    float* __restrict__ sfeat = smem + SM_FEAT + warp * (32 * FPAD);
    const float* sbnd = smem + SM_BND;

    // ---- per-lane params for point base+lane ----
    {
        const int idx = base + lane;
        float px = 2.0f, py = 2.0f, pz = 2.0f;
        if (idx < n) { px = p[idx*3]; py = p[idx*3+1]; pz = p[idx*3+2]; }

        int s = 0; bool valid = false;
        #pragma unroll
        for (int k = SS - 1; k >= 0; k--) {
            const float lx = sbnd[k*6+0], ly = sbnd[k*6+1], lz = sbnd[k*6+2];
            const float hx = sbnd[k*6+3], hy = sbnd[k*6+4], hz = sbnd[k*6+5];
            const bool in = (px > lx) & (px < hx) & (py > ly) & (py < hy) & (pz > lz) & (pz < hz);
            if (in) { s = k; valid = true; }
        }
        const float m = valid ? 1.0f : 0.0f;

        const float bx0 = sbnd[s*6+0], by0 = sbnd[s*6+1], bz0 = sbnd[s*6+2];
        const float bx1 = sbnd[s*6+3], by1 = sbnd[s*6+4], bz1 = sbnd[s*6+5];
        const float pnx = (px - bx0) / (bx1 - bx0) * 2.0f - 1.0f;
        const float pny = (py - by0) / (by1 - by0) * 2.0f - 1.0f;
        const float pnz = (pz - bz0) / (bz1 - bz0) * 2.0f - 1.0f;

        const float us[3] = { pnx, pnx, pny };
        const float vs[3] = { pny, pnz, pnz };
        #pragma unroll
        for (int t = 0; t < 3; t++) {
            const float x = (us[t] + 1.0f) * 0.5f * (float)(RR - 1);
            const float y = (vs[t] + 1.0f) * 0.5f * (float)(RR - 1);
            const float xf = fminf(fmaxf(floorf(x), 0.0f), (float)(RR - 2));
            const float yf = fminf(fmaxf(floorf(y), 0.0f), (float)(RR - 2));
            const float wx = x - xf, wy = y - yf;
            float4 q;
            q.x = m * (1.0f - wx) * (1.0f - wy);
            q.y = m * wx * (1.0f - wy);
            q.z = m * (1.0f - wx) * wy;
            q.w = m * wx * wy;
            *(float4*)&par[lane * 16 + t * 4] = q;
            const int off = ((s * RR + (int)yf) * RR + (int)xf) * CC;
            ((int*)par)[lane * 16 + 12 + t] = off;
        }
    }
    __syncwarp();

    ull h[16];
    float* __restrict__ row = sfeat + lane * FPAD;

    // ================= SDF branch =================
    gather32(pxy, pxz, pyz, par, sfeat, lane);
    __syncwarp();
    layer32(row, smem + SM_W0, smem + SM_B0, h);
    relu_store(row, h);
    layer32(row, smem + SM_W1, smem + SM_B1, h);

    float sdf;
    {
        float acc = smem[SM_BO];
        #pragma unroll
        for (int j = 0; j < 16; j++) {
            float a, b; unpack2(h[j], a, b);
            acc += fmaxf(a, 0.0f) * smem[SM_WOUT + 2*j];
            acc += fmaxf(b, 0.0f) * smem[SM_WOUT + 2*j + 1];
        }
        sdf = tanhf(acc);
    }
    __syncwarp();

    // ================= Color branch =================
    gather32(cxy, cxz, cyz, par, sfeat, lane);
    __syncwarp();
    layer32(row, smem + SM_CW0, smem + SM_CB0, h);
    relu_store(row, h);
    layer32(row, smem + SM_CW1, smem + SM_CB1, h);

    float rA = smem[SM_CBO + 0], gA = smem[SM_CBO + 1], bA = smem[SM_CBO + 2];
    #pragma unroll
    for (int j = 0; j < 16; j++) {
        float a, b; unpack2(h[j], a, b);
        const float ha = fmaxf(a, 0.0f), hb = fmaxf(b, 0.0f);
        rA += ha * smem[SM_CWOUT + (2*j)*3 + 0] + hb * smem[SM_CWOUT + (2*j+1)*3 + 0];
        gA += ha * smem[SM_CWOUT + (2*j)*3 + 1] + hb * smem[SM_CWOUT + (2*j+1)*3 + 1];
        bA += ha * smem[SM_CWOUT + (2*j)*3 + 2] + hb * smem[SM_CWOUT + (2*j+1)*3 + 2];
    }

    const int idx = base + lane;
    if (idx < n) {
        float4 o;
        o.x = 1.0f / (1.0f + expf(-rA));
        o.y = 1.0f / (1.0f + expf(-gA));
        o.z = 1.0f / (1.0f + expf(-bA));
        o.w = sdf;
        ((float4*)out)[idx] = o;
    }
}

extern "C" void kernel_launch(void* const* d_in, const int* in_sizes, int n_in,
                              void* d_out, int out_size) {
    const float* p          = (const float*)d_in[0];
    const float* boundaries = (const float*)d_in[1];
    const float* pxy        = (const float*)d_in[2];
    const float* pxz        = (const float*)d_in[3];
    const float* pyz        = (const float*)d_in[4];
    const float* cxy        = (const float*)d_in[5];
    const float* cxz        = (const float*)d_in[6];
    const float* cyz        = (const float*)d_in[7];
    const float* w0         = (const float*)d_in[8];
    const float* b0         = (const float*)d_in[9];
    const float* w1         = (const float*)d_in[10];
    const float* b1         = (const float*)d_in[11];
    const float* w_out      = (const float*)d_in[12];
    const float* b_out      = (const float*)d_in[13];
    const float* cw0        = (const float*)d_in[14];
    const float* cb0        = (const float*)d_in[15];
    const float* cw1        = (const float*)d_in[16];
    const float* cb1        = (const float*)d_in[17];
    const float* cw_out     = (const float*)d_in[18];
    const float* cb_out     = (const float*)d_in[19];

    const int n = in_sizes[0] / 3;
    float* out = (float*)d_out;

    const int smem_bytes = SMEM_FLOATS * (int)sizeof(float);
    cudaFuncSetAttribute(decoders_kernel,
                         cudaFuncAttributeMaxDynamicSharedMemorySize, smem_bytes);

    const int pts_per_block = WARPS * 32;   // 128
    const int blocks = (n + pts_per_block - 1) / pts_per_block;
    decoders_kernel<<<blocks, 128, smem_bytes>>>(
        p, boundaries, pxy, pxz, pyz, cxy, cxz, cyz,
        w0, b0, w1, b1, w_out, b_out,
        cw0, cb0, cw1, cb1, cw_out, cb_out,
        out, n);
}

// round 4
// speedup vs baseline: 1.3889x; 1.0051x over previous
#include <cuda_runtime.h>

typedef unsigned long long ull;

#define RR 256
#define CC 32
#define SS 8
#define HH 32
#define WARPS 4
#define FPAD 36

__constant__ float cW0[CC*HH], cW1[HH*HH], cCW0[CC*HH], cCW1[HH*HH];
__constant__ float cB0[HH], cB1[HH], cCB0[HH], cCB1[HH];
__constant__ float cWOUT[HH], cCWOUT[HH*3];
__constant__ float cBND[SS*6];
__constant__ float cBO[1], cCBO[3];

// shared memory: per-warp param block + feat transpose buffer only
#define SM_PAR   0                           // WARPS*32*16 = 2048 words
#define SM_FEAT  (SM_PAR + WARPS*32*16)
#define SMEM_FLOATS (SM_FEAT + WARPS*32*FPAD)   // 2048+4608 = 6656 words = 26624 B

__device__ __forceinline__ ull pack2(float lo, float hi) {
    ull d; asm("mov.b64 %0, {%1, %2};" : "=l"(d) : "f"(lo), "f"(hi)); return d;
}
__device__ __forceinline__ void unpack2(ull v, float& lo, float& hi) {
    asm("mov.b64 {%0, %1}, %2;" : "=f"(lo), "=f"(hi) : "l"(v));
}
__device__ __forceinline__ void fma2(ull& d, ull a, ull b) {
    asm("fma.rn.f32x2 %0, %1, %2, %0;" : "+l"(d) : "l"(a), "l"(b));
}

// one 32x32 layer; W/B are __constant__ arrays (direct indexing -> LDC/LDCU)
#define LAYER32(row, W, B, h)                                              \
    do {                                                                   \
        _Pragma("unroll")                                                  \
        for (int j = 0; j < 8; j++) {                                      \
            const ulonglong2 bv = *(const ulonglong2*)&B[j * 4];           \
            h[2*j] = bv.x; h[2*j+1] = bv.y;                                \
        }                                                                  \
        _Pragma("unroll")                                                  \
        for (int i4 = 0; i4 < 8; i4++) {                                   \
            const float4 f4 = *(const float4*)&(row)[i4 * 4];              \
            const float fk[4] = { f4.x, f4.y, f4.z, f4.w };                \
            _Pragma("unroll")                                              \
            for (int k = 0; k < 4; k++) {                                  \
                const ull a = pack2(fk[k], fk[k]);                         \
                _Pragma("unroll")                                          \
                for (int j = 0; j < 8; j++) {                              \
                    const ulonglong2 w =                                   \
                        *(const ulonglong2*)&W[(i4 * 4 + k) * HH + j * 4]; \
                    fma2(h[2*j],   a, w.x);                                \
                    fma2(h[2*j+1], a, w.y);                                \
                }                                                          \
            }                                                              \
        }                                                                  \
    } while (0)

__device__ __forceinline__ void relu_store(float* __restrict__ row, const ull (&h)[16])
{
    #pragma unroll
    for (int j = 0; j < 8; j++) {
        float a, b, c, d;
        unpack2(h[2*j], a, b); unpack2(h[2*j+1], c, d);
        float4 v;
        v.x = fmaxf(a, 0.0f); v.y = fmaxf(b, 0.0f);
        v.z = fmaxf(c, 0.0f); v.w = fmaxf(d, 0.0f);
        *(float4*)&row[j * 4] = v;
    }
}

// warp-cooperative gather: lane = channel, one point per iteration
__device__ __forceinline__ void gather32(
    const float* __restrict__ P0, const float* __restrict__ P1, const float* __restrict__ P2,
    const float* __restrict__ par, float* __restrict__ sfeat, int lane)
{
    #pragma unroll 4
    for (int pt = 0; pt < 32; pt++) {
        const float4 q0 = *(const float4*)&par[pt * 16 + 0];
        const float4 q1 = *(const float4*)&par[pt * 16 + 4];
        const float4 q2 = *(const float4*)&par[pt * 16 + 8];
        const int4  qo = *(const int4*) &par[pt * 16 + 12];
        const float* a = P0 + qo.x + lane;
        const float* b = P1 + qo.y + lane;
        const float* c = P2 + qo.z + lane;
        float f;
        f  = q0.x * a[0] + q0.y * a[CC] + q0.z * a[RR*CC] + q0.w * a[RR*CC + CC];
        f += q1.x * b[0] + q1.y * b[CC] + q1.z * b[RR*CC] + q1.w * b[RR*CC + CC];
        f += q2.x * c[0] + q2.y * c[CC] + q2.z * c[RR*CC] + q2.w * c[RR*CC + CC];
        sfeat[pt * FPAD + lane] = f;
    }
}

__global__ __launch_bounds__(128, 7) void decoders_kernel(
    const float* __restrict__ p,
    const float* __restrict__ pxy, const float* __restrict__ pxz, const float* __restrict__ pyz,
    const float* __restrict__ cxy, const float* __restrict__ cxz, const float* __restrict__ cyz,
    float* __restrict__ out, int n)
{
    extern __shared__ float smem[];
    const int tid = threadIdx.x;
    const int warp = tid >> 5, lane = tid & 31;
    const int base = (blockIdx.x * WARPS + warp) * 32;
    float* __restrict__ par   = smem + SM_PAR  + warp * (32 * 16);
    float* __restrict__ sfeat = smem + SM_FEAT + warp * (32 * FPAD);

    // ---- per-lane params for point base+lane ----
    {
        const int idx = base + lane;
        float px = 2.0f, py = 2.0f, pz = 2.0f;
        if (idx < n) { px = p[idx*3]; py = p[idx*3+1]; pz = p[idx*3+2]; }

        int s = 0; bool valid = false;
        #pragma unroll
        for (int k = SS - 1; k >= 0; k--) {
            const float lx = cBND[k*6+0], ly = cBND[k*6+1], lz = cBND[k*6+2];
            const float hx = cBND[k*6+3], hy = cBND[k*6+4], hz = cBND[k*6+5];
            const bool in = (px > lx) & (px < hx) & (py > ly) & (py < hy) & (pz > lz) & (pz < hz);
            if (in) { s = k; valid = true; }
        }
        const float m = valid ? 1.0f : 0.0f;

        const float bx0 = cBND[s*6+0], by0 = cBND[s*6+1], bz0 = cBND[s*6+2];
        const float bx1 = cBND[s*6+3], by1 = cBND[s*6+4], bz1 = cBND[s*6+5];
        const float pnx = (px - bx0) / (bx1 - bx0) * 2.0f - 1.0f;
        const float pny = (py - by0) / (by1 - by0) * 2.0f - 1.0f;
        const float pnz = (pz - bz0) / (bz1 - bz0) * 2.0f - 1.0f;

        const float us[3] = { pnx, pnx, pny };
        const float vs[3] = { pny, pnz, pnz };
        #pragma unroll
        for (int t = 0; t < 3; t++) {
            const float x = (us[t] + 1.0f) * 0.5f * (float)(RR - 1);
            const float y = (vs[t] + 1.0f) * 0.5f * (float)(RR - 1);
            const float xf = fminf(fmaxf(floorf(x), 0.0f), (float)(RR - 2));
            const float yf = fminf(fmaxf(floorf(y), 0.0f), (float)(RR - 2));
            const float wx = x - xf, wy = y - yf;
            float4 q;
            q.x = m * (1.0f - wx) * (1.0f - wy);
            q.y = m * wx * (1.0f - wy);
            q.z = m * (1.0f - wx) * wy;
            q.w = m * wx * wy;
            *(float4*)&par[lane * 16 + t * 4] = q;
            const int off = ((s * RR + (int)yf) * RR + (int)xf) * CC;
            ((int*)par)[lane * 16 + 12 + t] = off;
        }
    }
    __syncwarp();

    ull h[16];
    float* __restrict__ row = sfeat + lane * FPAD;

    // ================= SDF branch =================
    gather32(pxy, pxz, pyz, par, sfeat, lane);
    __syncwarp();
    LAYER32(row, cW0, cB0, h);
    relu_store(row, h);
    LAYER32(row, cW1, cB1, h);

    float sdf;
    {
        float acc = cBO[0];
        #pragma unroll
        for (int j = 0; j < 16; j++) {
            float a, b; unpack2(h[j], a, b);
            acc += fmaxf(a, 0.0f) * cWOUT[2*j];
            acc += fmaxf(b, 0.0f) * cWOUT[2*j + 1];
        }
        sdf = tanhf(acc);
    }
    __syncwarp();

    // ================= Color branch =================
    gather32(cxy, cxz, cyz, par, sfeat, lane);
    __syncwarp();
    LAYER32(row, cCW0, cCB0, h);
    relu_store(row, h);
    LAYER32(row, cCW1, cCB1, h);

    float rA = cCBO[0], gA = cCBO[1], bA = cCBO[2];
    #pragma unroll
    for (int j = 0; j < 16; j++) {
        float a, b; unpack2(h[j], a, b);
        const float ha = fmaxf(a, 0.0f), hb = fmaxf(b, 0.0f);
        rA += ha * cCWOUT[(2*j)*3 + 0] + hb * cCWOUT[(2*j+1)*3 + 0];
        gA += ha * cCWOUT[(2*j)*3 + 1] + hb * cCWOUT[(2*j+1)*3 + 1];
        bA += ha * cCWOUT[(2*j)*3 + 2] + hb * cCWOUT[(2*j+1)*3 + 2];
    }

    const int idx = base + lane;
    if (idx < n) {
        float4 o;
        o.x = 1.0f / (1.0f + expf(-rA));
        o.y = 1.0f / (1.0f + expf(-gA));
        o.z = 1.0f / (1.0f + expf(-bA));
        o.w = sdf;
        ((float4*)out)[idx] = o;
    }
}

extern "C" void kernel_launch(void* const* d_in, const int* in_sizes, int n_in,
                              void* d_out, int out_size) {
    const float* p          = (const float*)d_in[0];
    const float* boundaries = (const float*)d_in[1];
    const float* pxy        = (const float*)d_in[2];
    const float* pxz        = (const float*)d_in[3];
    const float* pyz        = (const float*)d_in[4];
    const float* cxy        = (const float*)d_in[5];
    const float* cxz        = (const float*)d_in[6];
    const float* cyz        = (const float*)d_in[7];

    // stage small params into __constant__ (device-to-device async copies)
    cudaMemcpyToSymbolAsync(cW0,    d_in[8],  CC*HH*4, 0, cudaMemcpyDeviceToDevice, 0);
    cudaMemcpyToSymbolAsync(cB0,    d_in[9],  HH*4,    0, cudaMemcpyDeviceToDevice, 0);
    cudaMemcpyToSymbolAsync(cW1,    d_in[10], HH*HH*4, 0, cudaMemcpyDeviceToDevice, 0);
    cudaMemcpyToSymbolAsync(cB1,    d_in[11], HH*4,    0, cudaMemcpyDeviceToDevice, 0);
    cudaMemcpyToSymbolAsync(cWOUT,  d_in[12], HH*4,    0, cudaMemcpyDeviceToDevice, 0);
    cudaMemcpyToSymbolAsync(cBO,    d_in[13], 4,       0, cudaMemcpyDeviceToDevice, 0);
    cudaMemcpyToSymbolAsync(cCW0,   d_in[14], CC*HH*4, 0, cudaMemcpyDeviceToDevice, 0);
    cudaMemcpyToSymbolAsync(cCB0,   d_in[15], HH*4,    0, cudaMemcpyDeviceToDevice, 0);
    cudaMemcpyToSymbolAsync(cCW1,   d_in[16], HH*HH*4, 0, cudaMemcpyDeviceToDevice, 0);
    cudaMemcpyToSymbolAsync(cCB1,   d_in[17], HH*4,    0, cudaMemcpyDeviceToDevice, 0);
    cudaMemcpyToSymbolAsync(cCWOUT, d_in[18], HH*3*4,  0, cudaMemcpyDeviceToDevice, 0);
    cudaMemcpyToSymbolAsync(cCBO,   d_in[19], 3*4,     0, cudaMemcpyDeviceToDevice, 0);
    cudaMemcpyToSymbolAsync(cBND,   boundaries, SS*6*4, 0, cudaMemcpyDeviceToDevice, 0);

    const int n = in_sizes[0] / 3;
    float* out = (float*)d_out;

    const int smem_bytes = SMEM_FLOATS * (int)sizeof(float);
    cudaFuncSetAttribute(decoders_kernel,
                         cudaFuncAttributeMaxDynamicSharedMemorySize, smem_bytes);

    const int pts_per_block = WARPS * 32;   // 128
    const int blocks = (n + pts_per_block - 1) / pts_per_block;
    decoders_kernel<<<blocks, 128, smem_bytes>>>(
        p, pxy, pxz, pyz, cxy, cxz, cyz, out, n);
}